// round 2
// baseline (speedup 1.0000x reference)
#include <cuda_runtime.h>
#include <cuda_bf16.h>
#include <cstdint>

// Problem: q[n,k] = (1/(1+dist(n,k))) / rowsum,  dist = ||x||^2+||c||^2-2 x.c
// N=65536, K=256, D=512, fp32 in/out. ALPHA=1 -> exponent is exactly 1.
#define NROWS 65536
#define KCL   256
#define DDIM  512
#define BM    128      // rows per CTA
#define BN    256      // clusters per CTA (all)
#define DC    32       // K-chunk (bf16 elems) per stage
#define NCH   (DDIM / DC)   // 16

// SMEM layout (bytes): two stages of A(128x32 bf16=8KB) + B(256x32 bf16=16KB)
#define SOFF_A0   0
#define SOFF_B0   8192
#define SOFF_A1   24576
#define SOFF_B1   32768
#define SOFF_X2   49152               // 128 floats
#define SOFF_C2   (SOFF_X2 + 512)     // 256 floats
#define SOFF_RS   (SOFF_C2 + 1024)    // 4 x 128 floats (per warp_n row partials)
#define SMEM_BYTES (SOFF_RS + 2048)

static __device__ __forceinline__ uint32_t smem_u32(const void* p) {
    uint32_t a;
    asm("{ .reg .u64 t; cvta.to.shared.u64 t, %1; cvt.u32.u64 %0, t; }"
        : "=r"(a) : "l"(p));
    return a;
}

static __device__ __forceinline__ uint32_t packbf(float a, float b) {
    __nv_bfloat162 h = __floats2bfloat162_rn(a, b);
    return *reinterpret_cast<uint32_t*>(&h);
}

static __device__ __forceinline__ void sts128(uint32_t addr, uint32_t p0, uint32_t p1,
                                              uint32_t p2, uint32_t p3) {
    asm volatile("st.shared.v4.b32 [%0], {%1, %2, %3, %4};"
                 :: "r"(addr), "r"(p0), "r"(p1), "r"(p2), "r"(p3) : "memory");
}

// 64B-row tile with XOR swizzle: 16B chunk column cc (0..3) of row r lives at
// r*64 + 16*(cc ^ ((r>>1)&3)).  Conflict-free for both STS.128 and ldmatrix.
static __device__ __forceinline__ uint32_t swz(uint32_t row, uint32_t cc) {
    return row * 64u + 16u * (cc ^ ((row >> 1) & 3u));
}

static __device__ __forceinline__ void ldmx4(uint32_t addr, uint32_t& r0, uint32_t& r1,
                                             uint32_t& r2, uint32_t& r3) {
    asm volatile("ldmatrix.sync.aligned.m8n8.x4.shared.b16 {%0,%1,%2,%3}, [%4];"
                 : "=r"(r0), "=r"(r1), "=r"(r2), "=r"(r3) : "r"(addr));
}

static __device__ __forceinline__ void mma16816(float* c, const uint32_t* a,
                                                uint32_t b0, uint32_t b1) {
    asm volatile(
        "mma.sync.aligned.m16n8k16.row.col.f32.bf16.bf16.f32 "
        "{%0,%1,%2,%3}, {%4,%5,%6,%7}, {%8,%9}, {%0,%1,%2,%3};"
        : "+f"(c[0]), "+f"(c[1]), "+f"(c[2]), "+f"(c[3])
        : "r"(a[0]), "r"(a[1]), "r"(a[2]), "r"(a[3]), "r"(b0), "r"(b1));
}

__global__ __launch_bounds__(512, 1)
void cluster_q_kernel(const float* __restrict__ X, const float* __restrict__ Cc,
                      float* __restrict__ Out)
{
    extern __shared__ char smem[];
    const uint32_t sb = smem_u32(smem);
    const int t      = threadIdx.x;
    const int lane   = t & 31;
    const int warp   = t >> 5;
    const int warp_m = warp & 3;        // row block  (32 rows)
    const int warp_n = warp >> 2;       // col block  (64 cols)
    const int m0     = blockIdx.x * BM;

    // ---- loader mapping (fixed across chunks) ----
    // A: 512 chunks of 8 floats; thread t owns chunk t: row t/4, kc t%4
    // B: 1024 chunks; thread t owns chunks t and t+512: rows t/4 and 128+t/4
    const int lrow  = t >> 2;           // 0..127
    const int lkc   = t & 3;            // 0..3  (8-float sub-chunk)
    const float* Asrc = X + (size_t)(m0 + lrow) * DDIM + lkc * 8;
    const float* Bsrc0 = Cc + (size_t)lrow * DDIM + lkc * 8;
    const float* Bsrc1 = Cc + (size_t)(128 + lrow) * DDIM + lkc * 8;
    const uint32_t aSto = swz((uint32_t)lrow, (uint32_t)lkc);
    const uint32_t bSto0 = swz((uint32_t)lrow, (uint32_t)lkc);
    const uint32_t bSto1 = swz((uint32_t)(128 + lrow), (uint32_t)lkc);

    float nA = 0.f, nB0 = 0.f, nB1 = 0.f;   // fp32 norm partials

    float acc[2][8][4];
    #pragma unroll
    for (int i = 0; i < 2; ++i)
        #pragma unroll
        for (int j = 0; j < 8; ++j)
            #pragma unroll
            for (int k = 0; k < 4; ++k) acc[i][j][k] = 0.f;

    float4 pa0, pa1, pb00, pb01, pb10, pb11;    // prefetch regs

    // g2r for chunk ch
    auto G2R = [&](int ch) {
        const float4* a = reinterpret_cast<const float4*>(Asrc + ch * DC);
        pa0 = a[0]; pa1 = a[1];
        const float4* b0 = reinterpret_cast<const float4*>(Bsrc0 + ch * DC);
        pb00 = b0[0]; pb01 = b0[1];
        const float4* b1 = reinterpret_cast<const float4*>(Bsrc1 + ch * DC);
        pb10 = b1[0]; pb11 = b1[1];
    };
    // regs -> smem stage s, accumulate norms
    auto R2S = [&](int s) {
        const uint32_t aT = sb + (s ? SOFF_A1 : SOFF_A0);
        const uint32_t bT = sb + (s ? SOFF_B1 : SOFF_B0);
        nA += pa0.x*pa0.x + pa0.y*pa0.y + pa0.z*pa0.z + pa0.w*pa0.w
            + pa1.x*pa1.x + pa1.y*pa1.y + pa1.z*pa1.z + pa1.w*pa1.w;
        sts128(aT + aSto, packbf(pa0.x, pa0.y), packbf(pa0.z, pa0.w),
                          packbf(pa1.x, pa1.y), packbf(pa1.z, pa1.w));
        nB0 += pb00.x*pb00.x + pb00.y*pb00.y + pb00.z*pb00.z + pb00.w*pb00.w
             + pb01.x*pb01.x + pb01.y*pb01.y + pb01.z*pb01.z + pb01.w*pb01.w;
        sts128(bT + bSto0, packbf(pb00.x, pb00.y), packbf(pb00.z, pb00.w),
                           packbf(pb01.x, pb01.y), packbf(pb01.z, pb01.w));
        nB1 += pb10.x*pb10.x + pb10.y*pb10.y + pb10.z*pb10.z + pb10.w*pb10.w
             + pb11.x*pb11.x + pb11.y*pb11.y + pb11.z*pb11.z + pb11.w*pb11.w;
        sts128(bT + bSto1, packbf(pb10.x, pb10.y), packbf(pb10.z, pb10.w),
                           packbf(pb11.x, pb11.y), packbf(pb11.z, pb11.w));
    };

    // ldmatrix lane addressing (constant parts)
    const uint32_t aRowBase = (uint32_t)(warp_m * 32 + (lane & 15));
    const uint32_t aCCoff   = (uint32_t)(lane >> 4);             // 0/1
    const uint32_t bRowBase = (uint32_t)(warp_n * 64 + (lane & 7) + ((lane >> 4) << 3));
    const uint32_t bCCoff   = (uint32_t)((lane >> 3) & 1);       // 0/1

    auto COMPUTE = [&](int s) {
        const uint32_t aT = sb + (s ? SOFF_A1 : SOFF_A0);
        const uint32_t bT = sb + (s ? SOFF_B1 : SOFF_B0);
        #pragma unroll
        for (int ks = 0; ks < 2; ++ks) {               // 2 x k16 per chunk
            const uint32_t ccA = (uint32_t)(ks * 2) + aCCoff;
            const uint32_t ccB = (uint32_t)(ks * 2) + bCCoff;
            uint32_t af[2][4];
            #pragma unroll
            for (int mi = 0; mi < 2; ++mi) {
                uint32_t r = aRowBase + mi * 16;
                ldmx4(aT + swz(r, ccA), af[mi][0], af[mi][1], af[mi][2], af[mi][3]);
            }
            #pragma unroll
            for (int nb = 0; nb < 4; ++nb) {           // 16 cols per ldmatrix
                uint32_t b0, b1, b2, b3;
                uint32_t r = bRowBase + nb * 16;
                ldmx4(bT + swz(r, ccB), b0, b1, b2, b3);
                #pragma unroll
                for (int mi = 0; mi < 2; ++mi) {
                    mma16816(acc[mi][2 * nb + 0], af[mi], b0, b1);
                    mma16816(acc[mi][2 * nb + 1], af[mi], b2, b3);
                }
            }
        }
    };

    // -------- pipelined mainloop --------
    G2R(0); R2S(0);
    G2R(1);
    __syncthreads();
    #pragma unroll 1
    for (int ch = 0; ch < NCH; ++ch) {
        if (ch + 1 < NCH) R2S((ch + 1) & 1);
        if (ch + 2 < NCH) G2R(ch + 2);
        __syncthreads();
        COMPUTE(ch & 1);
        __syncthreads();
    }

    // -------- norms -> smem --------
    float* x2s = reinterpret_cast<float*>(smem + SOFF_X2);
    float* c2s = reinterpret_cast<float*>(smem + SOFF_C2);
    nA  += __shfl_xor_sync(0xffffffffu, nA, 1);  nA  += __shfl_xor_sync(0xffffffffu, nA, 2);
    nB0 += __shfl_xor_sync(0xffffffffu, nB0, 1); nB0 += __shfl_xor_sync(0xffffffffu, nB0, 2);
    nB1 += __shfl_xor_sync(0xffffffffu, nB1, 1); nB1 += __shfl_xor_sync(0xffffffffu, nB1, 2);
    if ((t & 3) == 0) {
        x2s[lrow]       = nA;
        c2s[lrow]       = nB0;
        c2s[128 + lrow] = nB1;
    }
    __syncthreads();

    // -------- epilogue pass 1: q = 1/(1+dist), row partial sums --------
    const int rbase = warp_m * 32 + (lane >> 2);     // +8 for second half, +16 for mi=1
    float qs[2][2] = {{0.f, 0.f}, {0.f, 0.f}};
    #pragma unroll
    for (int mi = 0; mi < 2; ++mi) {
        const float x2a = x2s[rbase + mi * 16];
        const float x2b = x2s[rbase + mi * 16 + 8];
        #pragma unroll
        for (int ni = 0; ni < 8; ++ni) {
            const int col = warp_n * 64 + ni * 8 + (lane & 3) * 2;
            const float c2a = c2s[col], c2b = c2s[col + 1];
            float q0 = __fdividef(1.f, 1.f + fmaxf(x2a + c2a - 2.f * acc[mi][ni][0], 0.f));
            float q1 = __fdividef(1.f, 1.f + fmaxf(x2a + c2b - 2.f * acc[mi][ni][1], 0.f));
            float q2 = __fdividef(1.f, 1.f + fmaxf(x2b + c2a - 2.f * acc[mi][ni][2], 0.f));
            float q3 = __fdividef(1.f, 1.f + fmaxf(x2b + c2b - 2.f * acc[mi][ni][3], 0.f));
            acc[mi][ni][0] = q0; acc[mi][ni][1] = q1;
            acc[mi][ni][2] = q2; acc[mi][ni][3] = q3;
            qs[mi][0] += q0 + q1;
            qs[mi][1] += q2 + q3;
        }
    }
    float* rs = reinterpret_cast<float*>(smem + SOFF_RS);
    #pragma unroll
    for (int mi = 0; mi < 2; ++mi) {
        #pragma unroll
        for (int h = 0; h < 2; ++h) {
            float v = qs[mi][h];
            v += __shfl_xor_sync(0xffffffffu, v, 1);
            v += __shfl_xor_sync(0xffffffffu, v, 2);
            if ((lane & 3) == 0)
                rs[warp_n * 128 + rbase + mi * 16 + h * 8] = v;
        }
    }
    __syncthreads();

    // -------- epilogue pass 2: scale + store --------
    #pragma unroll
    for (int mi = 0; mi < 2; ++mi) {
        #pragma unroll
        for (int h = 0; h < 2; ++h) {
            const int r = rbase + mi * 16 + h * 8;
            const float inv = __fdividef(1.f,
                rs[r] + rs[128 + r] + rs[256 + r] + rs[384 + r]);
            float* orow = Out + (size_t)(m0 + r) * KCL + warp_n * 64 + (lane & 3) * 2;
            #pragma unroll
            for (int ni = 0; ni < 8; ++ni) {
                float2 v;
                v.x = acc[mi][ni][2 * h + 0] * inv;
                v.y = acc[mi][ni][2 * h + 1] * inv;
                *reinterpret_cast<float2*>(orow + ni * 8) = v;
            }
        }
    }
}

extern "C" void kernel_launch(void* const* d_in, const int* in_sizes, int n_in,
                              void* d_out, int out_size)
{
    const float* X  = (const float*)d_in[0];
    const float* Cc = (const float*)d_in[1];
    if (n_in >= 2 && in_sizes[0] < in_sizes[1]) {   // robustness: X is the big one
        const float* tmp = X; X = Cc; Cc = tmp;
    }
    float* Out = (float*)d_out;

    static int smem_set = 0;
    if (!smem_set) {
        cudaFuncSetAttribute(cluster_q_kernel,
                             cudaFuncAttributeMaxDynamicSharedMemorySize, SMEM_BYTES);
        smem_set = 1;
    }
    cluster_q_kernel<<<NROWS / BM, 512, SMEM_BYTES>>>(X, Cc, Out);
}